// round 9
// baseline (speedup 1.0000x reference)
#include <cuda_runtime.h>
#include <cstdint>

#define NODES_MAX 50000
#define F 128

typedef unsigned long long ull;

// Scratch (no runtime allocation allowed)
__device__ float g_P[NODES_MAX * F];       // h @ W1h^T + b1
__device__ float g_sums[NODES_MAX * F];    // segment sums of leaky acts
__device__ float g_counts[NODES_MAX];      // in-degree
__device__ float g_W1T[F * F];             // [k][c] = W1[c*131 + k]
__device__ float g_W2T[256 * F];           // [k][c] = W2[c*256 + k]

// ---------------------------------------------------------------------------
// Prep: transpose weights, zero accumulators
// ---------------------------------------------------------------------------
__global__ void prep_kernel(const float* __restrict__ W1,
                            const float* __restrict__ W2,
                            int n_nodes)
{
    int idx = blockIdx.x * blockDim.x + threadIdx.x;
    int stride = gridDim.x * blockDim.x;

    for (int i = idx; i < F * F; i += stride) {
        int c = i >> 7, k = i & 127;
        g_W1T[k * F + c] = W1[c * 131 + k];
    }
    for (int i = idx; i < 256 * F; i += stride) {
        int c = i & 127, k = i >> 7;
        g_W2T[k * F + c] = W2[c * 256 + k];
    }
    int nsum4 = (n_nodes * F) >> 2;
    float4* s4 = reinterpret_cast<float4*>(g_sums);
    float4 z = make_float4(0.f, 0.f, 0.f, 0.f);
    for (int i = idx; i < nsum4; i += stride) s4[i] = z;
    for (int i = idx; i < n_nodes; i += stride) g_counts[i] = 0.f;
}

// ---------------------------------------------------------------------------
// Core GEMM tile: FFMA2 inner loop with ZERO mov.b64 packing.
// A tile staged DUPLICATED in smem (row m stored as {a,a} 8-byte pairs) so
// the broadcast operand loads directly as 64-bit lanes; B pairs load as
// natural double2. 128x128 block, 8x8 micro-tile, BK=8, double-buffered.
// KTOT = 256: k<128 from A1, k>=128 from A2 scaled by 1/max(count,1).
// ---------------------------------------------------------------------------
#define AROW 264   // padded floats per A k-row (128 dup pairs = 256 + 8 pad)

template<int KTOT, bool RELU>
__device__ __forceinline__ void gemm_tile(
    const float* __restrict__ A1, const float* __restrict__ A2,
    const float* __restrict__ Bt, const float* __restrict__ bias,
    float* __restrict__ out, int M, int row0)
{
    __shared__ float As[2][8][AROW];   // dup image: row m -> floats [2m,2m+1]
    __shared__ float Bs[2][8][128];

    const int tid = threadIdx.x;
    const int tx = tid & 15;
    const int ty = tid >> 4;

    const int lm = tid >> 1;           // 0..127 row within tile
    const int lk = (tid & 1) * 4;      // 0 or 4
    const int grow = row0 + lm;
    const bool arow_ok = (grow < M);

    const int bk = tid >> 5;           // 0..7
    const int bc = (tid & 31) * 4;

    float inv = 1.0f;
    if (KTOT == 256)
        inv = arow_ok ? (1.0f / fmaxf(g_counts[grow], 1.0f)) : 0.0f;

    ull acc[8][4];
    #pragma unroll
    for (int i = 0; i < 8; i++)
        #pragma unroll
        for (int j = 0; j < 4; j++) acc[i][j] = 0ull;

    auto loadA = [&](int k0) -> float4 {
        float4 v = make_float4(0.f, 0.f, 0.f, 0.f);
        if (arow_ok) {
            if (KTOT == 256 && k0 >= 128) {
                v = *(const float4*)(A2 + (long)grow * 128 + (k0 - 128) + lk);
                v.x *= inv; v.y *= inv; v.z *= inv; v.w *= inv;
            } else {
                v = *(const float4*)(A1 + (long)grow * 128 + k0 + lk);
            }
        }
        return v;
    };
    auto loadB = [&](int k0) -> float4 {
        return *(const float4*)(Bt + (k0 + bk) * 128 + bc);
    };
    auto storeS = [&](int b, float4 ra, float4 rb) {
        float f[4] = {ra.x, ra.y, ra.z, ra.w};
        #pragma unroll
        for (int t = 0; t < 4; t++) {
            ull d;
            asm("mov.b64 %0, {%1, %1};" : "=l"(d) : "f"(f[t]));   // staging only
            *(ull*)&As[b][lk + t][2 * lm] = d;
        }
        *(float4*)&Bs[b][bk][bc] = rb;
    };
    auto compute = [&](const float (*As_)[AROW], const float (*Bs_)[128]) {
        #pragma unroll
        for (int k = 0; k < 8; k++) {
            const ull* arow = (const ull*)&As_[k][0];
            ulonglong2 a01 = *(const ulonglong2*)&arow[ty * 4 + 0];
            ulonglong2 a23 = *(const ulonglong2*)&arow[ty * 4 + 2];
            ulonglong2 a45 = *(const ulonglong2*)&arow[64 + ty * 4 + 0];
            ulonglong2 a67 = *(const ulonglong2*)&arow[64 + ty * 4 + 2];
            ull ad[8] = {a01.x, a01.y, a23.x, a23.y, a45.x, a45.y, a67.x, a67.y};
            double2 b01 = *(const double2*)&Bs_[k][tx * 4];
            double2 b23 = *(const double2*)&Bs_[k][64 + tx * 4];
            ull bp[4];
            bp[0] = __double_as_longlong(b01.x);
            bp[1] = __double_as_longlong(b01.y);
            bp[2] = __double_as_longlong(b23.x);
            bp[3] = __double_as_longlong(b23.y);
            #pragma unroll
            for (int i = 0; i < 8; i++)
                #pragma unroll
                for (int j = 0; j < 4; j++)
                    asm("fma.rn.f32x2 %0, %1, %2, %0;"
                        : "+l"(acc[i][j]) : "l"(ad[i]), "l"(bp[j]));
        }
    };

    // prologue: fill buffer 0
    storeS(0, loadA(0), loadB(0));
    __syncthreads();

    #pragma unroll 1
    for (int k0 = 0; k0 < KTOT; k0 += 16) {
        {
            float4 ra, rb;
            bool nxt = (k0 + 8) < KTOT;
            if (nxt) { ra = loadA(k0 + 8); rb = loadB(k0 + 8); }
            compute(As[0], Bs[0]);
            if (nxt) {
                storeS(1, ra, rb);
                __syncthreads();
            }
        }
        if ((k0 + 8) < KTOT) {
            float4 ra, rb;
            bool nxt = (k0 + 16) < KTOT;
            if (nxt) { ra = loadA(k0 + 16); rb = loadB(k0 + 16); }
            compute(As[1], Bs[1]);
            if (nxt) {
                storeS(0, ra, rb);
                __syncthreads();
            }
        }
    }

    const int c0 = tx * 4;
    const int c1 = 64 + tx * 4;
    float4 bias0 = *(const float4*)(bias + c0);
    float4 bias1 = *(const float4*)(bias + c1);

    #pragma unroll
    for (int i = 0; i < 8; i++) {
        int gr = row0 + ((i < 4) ? (ty * 4 + i) : (64 + ty * 4 + i - 4));
        if (gr >= M) continue;
        float4 v0, v1;
        asm("mov.b64 {%0, %1}, %2;" : "=f"(v0.x), "=f"(v0.y) : "l"(acc[i][0]));
        asm("mov.b64 {%0, %1}, %2;" : "=f"(v0.z), "=f"(v0.w) : "l"(acc[i][1]));
        asm("mov.b64 {%0, %1}, %2;" : "=f"(v1.x), "=f"(v1.y) : "l"(acc[i][2]));
        asm("mov.b64 {%0, %1}, %2;" : "=f"(v1.z), "=f"(v1.w) : "l"(acc[i][3]));
        v0.x += bias0.x; v0.y += bias0.y; v0.z += bias0.z; v0.w += bias0.w;
        v1.x += bias1.x; v1.y += bias1.y; v1.z += bias1.z; v1.w += bias1.w;
        if (RELU) {
            v0.x = fmaxf(v0.x, 0.f); v0.y = fmaxf(v0.y, 0.f);
            v0.z = fmaxf(v0.z, 0.f); v0.w = fmaxf(v0.w, 0.f);
            v1.x = fmaxf(v1.x, 0.f); v1.y = fmaxf(v1.y, 0.f);
            v1.z = fmaxf(v1.z, 0.f); v1.w = fmaxf(v1.w, 0.f);
        }
        *(float4*)(out + (long)gr * 128 + c0) = v0;
        *(float4*)(out + (long)gr * 128 + c1) = v1;
    }
}

// ---------------------------------------------------------------------------
// GEMM1: g_P = h @ W1h^T + b1
// ---------------------------------------------------------------------------
__global__ __launch_bounds__(256) void gemm1_kernel(
    const float* __restrict__ h, const float* __restrict__ b1, int M)
{
    gemm_tile<128, false>(h, nullptr, g_W1T, b1, g_P, M, blockIdx.x * 128);
}

// ---------------------------------------------------------------------------
// Edge kernel (proven r6): one warp per edge, x4 unrolled grid-stride,
// red.global.add.v4.f32 scatter into g_sums, count bump by lane 0.
// ---------------------------------------------------------------------------
__global__ __launch_bounds__(256) void edge_kernel(
    const int* __restrict__ src, const int* __restrict__ dst,
    const float* __restrict__ ew, const float* __restrict__ W1, int E)
{
    __shared__ float cw[3][128];
    for (int i = threadIdx.x; i < 384; i += 256) {
        int t = i >> 7, j = i & 127;
        cw[t][j] = W1[j * 131 + 128 + t];
    }
    __syncthreads();

    const int lane = threadIdx.x & 31;
    const int col  = lane * 4;
    const float4 cA = *(const float4*)&cw[0][col];
    const float4 cB = *(const float4*)&cw[1][col];
    const float4 cC = *(const float4*)&cw[2][col];

    const int gwarp  = (blockIdx.x * 256 + threadIdx.x) >> 5;
    const int nwarps = (gridDim.x * 256) >> 5;

    for (int e0 = gwarp; e0 < E; e0 += nwarps * 4) {
        int   se[4], de[4];
        float w0[4], w1[4], w2[4];
        float4 p[4];
        bool  v[4];

        #pragma unroll
        for (int u = 0; u < 4; u++) {
            int e = e0 + u * nwarps;
            v[u] = (e < E);
            if (v[u]) {
                se[u] = src[e];
                de[u] = dst[e];
                w0[u] = ew[e * 3 + 0];
                w1[u] = ew[e * 3 + 1];
                w2[u] = ew[e * 3 + 2];
            }
        }
        #pragma unroll
        for (int u = 0; u < 4; u++)
            if (v[u]) p[u] = *(const float4*)(g_P + (long)se[u] * 128 + col);

        #pragma unroll
        for (int u = 0; u < 4; u++) {
            if (!v[u]) continue;
            float t0 = p[u].x + w0[u] * cA.x + w1[u] * cB.x + w2[u] * cC.x;
            float t1 = p[u].y + w0[u] * cA.y + w1[u] * cB.y + w2[u] * cC.y;
            float t2 = p[u].z + w0[u] * cA.z + w1[u] * cB.z + w2[u] * cC.z;
            float t3 = p[u].w + w0[u] * cA.w + w1[u] * cB.w + w2[u] * cC.w;
            t0 = (t0 < 0.f) ? 0.01f * t0 : t0;
            t1 = (t1 < 0.f) ? 0.01f * t1 : t1;
            t2 = (t2 < 0.f) ? 0.01f * t2 : t2;
            t3 = (t3 < 0.f) ? 0.01f * t3 : t3;
            float* addr = g_sums + (long)de[u] * 128 + col;
            asm volatile("red.global.add.v4.f32 [%0], {%1, %2, %3, %4};"
                         :: "l"(addr), "f"(t0), "f"(t1), "f"(t2), "f"(t3)
                         : "memory");
            if (lane == 0) atomicAdd(&g_counts[de[u]], 1.0f);
        }
    }
}

// ---------------------------------------------------------------------------
// GEMM2 (K=256): out = relu( [h | g_sums*inv_count] @ W2^T + b2 )
// ---------------------------------------------------------------------------
__global__ __launch_bounds__(256) void gemm2_kernel(
    const float* __restrict__ h, const float* __restrict__ b2,
    float* __restrict__ out, int M)
{
    gemm_tile<256, true>(h, g_sums, g_W2T, b2, out, M, blockIdx.x * 128);
}

// ---------------------------------------------------------------------------
extern "C" void kernel_launch(void* const* d_in, const int* in_sizes, int n_in,
                              void* d_out, int out_size)
{
    const float* h    = (const float*)d_in[0];
    const int*   esrc = (const int*)  d_in[1];
    const int*   edst = (const int*)  d_in[2];
    const float* ew   = (const float*)d_in[3];
    const float* W1   = (const float*)d_in[4];
    const float* b1   = (const float*)d_in[5];
    const float* W2   = (const float*)d_in[6];
    const float* b2   = (const float*)d_in[7];
    float* out = (float*)d_out;

    int M = in_sizes[0] / 128;    // 50000 nodes
    int E = in_sizes[1];          // 800000 edges
    int nT = (M + 127) / 128;     // 391 row tiles

    prep_kernel<<<512, 256>>>(W1, W2, M);
    gemm1_kernel<<<nT, 256>>>(h, b1, M);
    edge_kernel<<<1480, 256>>>(esrc, edst, ew, W1, E);
    gemm2_kernel<<<nT, 256>>>(h, b2, out, M);
}

// round 12
// speedup vs baseline: 1.3352x; 1.3352x over previous
#include <cuda_runtime.h>
#include <cuda_bf16.h>
#include <cstdint>

#define NODES_MAX 50000
#define F 128

// Scratch (no runtime allocation allowed)
__device__ float g_P[NODES_MAX * F];       // h @ W1h^T + b1
__device__ float g_sums[NODES_MAX * F];    // segment sums of leaky acts
__device__ float g_counts[NODES_MAX];      // in-degree
__device__ __align__(16) unsigned short g_W1hi[128 * 128];  // [n][k] bf16 hi
__device__ __align__(16) unsigned short g_W1lo[128 * 128];
__device__ __align__(16) unsigned short g_W2hi[128 * 256];
__device__ __align__(16) unsigned short g_W2lo[128 * 256];

// ---------------------------------------------------------------------------
// Prep: bf16 hi/lo split of weights ([n][k] row-major), zero accumulators
// ---------------------------------------------------------------------------
__global__ void prep_kernel(const float* __restrict__ W1,
                            const float* __restrict__ W2, int n_nodes)
{
    int idx = blockIdx.x * blockDim.x + threadIdx.x;
    int stride = gridDim.x * blockDim.x;

    for (int i = idx; i < 128 * 128; i += stride) {
        int n = i >> 7, k = i & 127;
        float w = W1[n * 131 + k];
        __nv_bfloat16 h = __float2bfloat16(w);
        g_W1hi[i] = __bfloat16_as_ushort(h);
        g_W1lo[i] = __bfloat16_as_ushort(__float2bfloat16(w - __bfloat162float(h)));
    }
    for (int i = idx; i < 128 * 256; i += stride) {
        float w = W2[i];                       // already [n][k] row-major
        __nv_bfloat16 h = __float2bfloat16(w);
        g_W2hi[i] = __bfloat16_as_ushort(h);
        g_W2lo[i] = __bfloat16_as_ushort(__float2bfloat16(w - __bfloat162float(h)));
    }
    int nsum4 = (n_nodes * F) >> 2;
    float4* s4 = reinterpret_cast<float4*>(g_sums);
    float4 z = make_float4(0.f, 0.f, 0.f, 0.f);
    for (int i = idx; i < nsum4; i += stride) s4[i] = z;
    for (int i = idx; i < n_nodes; i += stride) g_counts[i] = 0.f;
}

// ---------------------------------------------------------------------------
// mma.sync m16n8k16 bf16 (A row, B col), fp32 accumulate
// ---------------------------------------------------------------------------
__device__ __forceinline__ void mma_bf16(float c[4], const uint32_t a[4],
                                         const uint32_t b[2])
{
    asm volatile(
        "mma.sync.aligned.m16n8k16.row.col.f32.bf16.bf16.f32 "
        "{%0,%1,%2,%3}, {%4,%5,%6,%7}, {%8,%9}, {%0,%1,%2,%3};"
        : "+f"(c[0]), "+f"(c[1]), "+f"(c[2]), "+f"(c[3])
        : "r"(a[0]), "r"(a[1]), "r"(a[2]), "r"(a[3]), "r"(b[0]), "r"(b[1]));
}

// ---------------------------------------------------------------------------
// Tensor-core GEMM (HMMA, bf16x3): C[row0:+128][0:128] = A(Mx128..256) @ B^T.
// WSEL=1: B = g_W1 images (KTOT=128), out = g_P.
// WSEL=2: B = g_W2 images (KTOT=256), A k>=128 from g_sums * 1/max(cnt,1),
//         out = kernel arg. ALL device globals bound in device code.
// 256 thr = 8 warps (2x4), warp tile 64x32, K-slab 32, smem stride 40 bf16.
// ---------------------------------------------------------------------------
#define KS_STRIDE 40

template<int KTOT, bool RELU, int WSEL>
__global__ __launch_bounds__(256, 1) void gemm_mma_kernel(
    const float* __restrict__ A1, const float* __restrict__ bias,
    float* __restrict__ out_arg, int M)
{
    const unsigned short* __restrict__ Bhi_g = (WSEL == 1) ? g_W1hi : g_W2hi;
    const unsigned short* __restrict__ Blo_g = (WSEL == 1) ? g_W1lo : g_W2lo;
    const float* __restrict__ A2 = g_sums;
    float* __restrict__ out = (WSEL == 1) ? g_P : out_arg;

    __shared__ __align__(16) unsigned short sAhi[128 * KS_STRIDE];
    __shared__ __align__(16) unsigned short sAlo[128 * KS_STRIDE];
    __shared__ __align__(16) unsigned short sBhi[128 * KS_STRIDE];
    __shared__ __align__(16) unsigned short sBlo[128 * KS_STRIDE];

    const int tid = threadIdx.x;
    const int row0 = blockIdx.x * 128;
    const int wid = tid >> 5, lane = tid & 31;
    const int wm = wid >> 2, wn = wid & 3;   // warp tile: rows wm*64, cols wn*32
    const int g = lane >> 2, t4 = lane & 3;

    // staging assignment: thread -> (row, k-half of 16)
    const int srow = tid >> 1;
    const int skh = (tid & 1) * 16;
    const int grow = row0 + srow;
    const bool rowok = grow < M;
    float inv = 1.f;
    if (KTOT == 256) inv = rowok ? (1.f / fmaxf(g_counts[grow], 1.f)) : 0.f;

    float acc[4][4][4];
    #pragma unroll
    for (int i = 0; i < 4; i++)
        #pragma unroll
        for (int j = 0; j < 4; j++)
            #pragma unroll
            for (int q = 0; q < 4; q++) acc[i][j][q] = 0.f;

    #pragma unroll 1
    for (int k0 = 0; k0 < KTOT; k0 += 32) {
        // ---- stage A: fp32 -> bf16 hi/lo into padded smem ----
        {
            float f[16];
            #pragma unroll
            for (int q = 0; q < 16; q++) f[q] = 0.f;
            if (rowok) {
                const bool second = (KTOT == 256) && (k0 >= 128);
                const float* src = second
                    ? (A2 + (long)grow * 128 + (k0 - 128) + skh)
                    : (A1 + (long)grow * 128 + k0 + skh);
                const float sc = second ? inv : 1.f;
                #pragma unroll
                for (int q = 0; q < 4; q++) {
                    float4 v = *(const float4*)(src + q * 4);
                    f[q * 4 + 0] = v.x * sc; f[q * 4 + 1] = v.y * sc;
                    f[q * 4 + 2] = v.z * sc; f[q * 4 + 3] = v.w * sc;
                }
            }
            uint32_t ph[8], pl[8];
            #pragma unroll
            for (int q = 0; q < 8; q++) {
                __nv_bfloat16 h0 = __float2bfloat16(f[2 * q]);
                __nv_bfloat16 h1 = __float2bfloat16(f[2 * q + 1]);
                unsigned short l0 = __bfloat16_as_ushort(
                    __float2bfloat16(f[2 * q] - __bfloat162float(h0)));
                unsigned short l1 = __bfloat16_as_ushort(
                    __float2bfloat16(f[2 * q + 1] - __bfloat162float(h1)));
                ph[q] = (uint32_t)__bfloat16_as_ushort(h0) |
                        ((uint32_t)__bfloat16_as_ushort(h1) << 16);
                pl[q] = (uint32_t)l0 | ((uint32_t)l1 << 16);
            }
            uint4* dh = (uint4*)&sAhi[srow * KS_STRIDE + skh];
            uint4* dl = (uint4*)&sAlo[srow * KS_STRIDE + skh];
            dh[0] = make_uint4(ph[0], ph[1], ph[2], ph[3]);
            dh[1] = make_uint4(ph[4], ph[5], ph[6], ph[7]);
            dl[0] = make_uint4(pl[0], pl[1], pl[2], pl[3]);
            dl[1] = make_uint4(pl[4], pl[5], pl[6], pl[7]);
        }
        // ---- stage B: straight copy of pre-split images ----
        {
            const unsigned short* bh = Bhi_g + (long)srow * KTOT + k0 + skh;
            const unsigned short* bl = Blo_g + (long)srow * KTOT + k0 + skh;
            uint4* dh = (uint4*)&sBhi[srow * KS_STRIDE + skh];
            uint4* dl = (uint4*)&sBlo[srow * KS_STRIDE + skh];
            dh[0] = *(const uint4*)bh; dh[1] = *(const uint4*)(bh + 8);
            dl[0] = *(const uint4*)bl; dl[1] = *(const uint4*)(bl + 8);
        }
        __syncthreads();

        #pragma unroll
        for (int ks = 0; ks < 32; ks += 16) {
            uint32_t ah[4][4], al[4][4];
            #pragma unroll
            for (int mt = 0; mt < 4; mt++) {
                int o = (wm * 64 + mt * 16 + g) * KS_STRIDE + ks + t4 * 2;
                ah[mt][0] = *(const uint32_t*)&sAhi[o];
                ah[mt][1] = *(const uint32_t*)&sAhi[o + 8 * KS_STRIDE];
                ah[mt][2] = *(const uint32_t*)&sAhi[o + 8];
                ah[mt][3] = *(const uint32_t*)&sAhi[o + 8 * KS_STRIDE + 8];
                al[mt][0] = *(const uint32_t*)&sAlo[o];
                al[mt][1] = *(const uint32_t*)&sAlo[o + 8 * KS_STRIDE];
                al[mt][2] = *(const uint32_t*)&sAlo[o + 8];
                al[mt][3] = *(const uint32_t*)&sAlo[o + 8 * KS_STRIDE + 8];
            }
            uint32_t bh[4][2], bl[4][2];
            #pragma unroll
            for (int nt = 0; nt < 4; nt++) {
                int o = (wn * 32 + nt * 8 + g) * KS_STRIDE + ks + t4 * 2;
                bh[nt][0] = *(const uint32_t*)&sBhi[o];
                bh[nt][1] = *(const uint32_t*)&sBhi[o + 8];
                bl[nt][0] = *(const uint32_t*)&sBlo[o];
                bl[nt][1] = *(const uint32_t*)&sBlo[o + 8];
            }
            #pragma unroll
            for (int mt = 0; mt < 4; mt++)
                #pragma unroll
                for (int nt = 0; nt < 4; nt++) {
                    mma_bf16(acc[mt][nt], ah[mt], bh[nt]);
                    mma_bf16(acc[mt][nt], ah[mt], bl[nt]);
                    mma_bf16(acc[mt][nt], al[mt], bh[nt]);
                }
        }
        __syncthreads();
    }

    // ---- epilogue: fragment rows (g, g+8), cols t4*2..+1 per 16x8 tile ----
    #pragma unroll
    for (int mt = 0; mt < 4; mt++) {
        int r0_ = row0 + wm * 64 + mt * 16 + g;
        int r1_ = r0_ + 8;
        #pragma unroll
        for (int nt = 0; nt < 4; nt++) {
            int c = wn * 32 + nt * 8 + t4 * 2;
            float b0 = bias[c], b1 = bias[c + 1];
            float v0 = acc[mt][nt][0] + b0, v1 = acc[mt][nt][1] + b1;
            float v2 = acc[mt][nt][2] + b0, v3 = acc[mt][nt][3] + b1;
            if (RELU) {
                v0 = fmaxf(v0, 0.f); v1 = fmaxf(v1, 0.f);
                v2 = fmaxf(v2, 0.f); v3 = fmaxf(v3, 0.f);
            }
            if (r0_ < M) *(float2*)(out + (long)r0_ * 128 + c) = make_float2(v0, v1);
            if (r1_ < M) *(float2*)(out + (long)r1_ * 128 + c) = make_float2(v2, v3);
        }
    }
}

// ---------------------------------------------------------------------------
// Edge kernel (proven r6): one warp per edge, x4 unrolled grid-stride,
// red.global.add.v4.f32 scatter into g_sums, count bump by lane 0.
// ---------------------------------------------------------------------------
__global__ __launch_bounds__(256) void edge_kernel(
    const int* __restrict__ src, const int* __restrict__ dst,
    const float* __restrict__ ew, const float* __restrict__ W1, int E)
{
    __shared__ float cw[3][128];
    for (int i = threadIdx.x; i < 384; i += 256) {
        int t = i >> 7, j = i & 127;
        cw[t][j] = W1[j * 131 + 128 + t];
    }
    __syncthreads();

    const int lane = threadIdx.x & 31;
    const int col  = lane * 4;
    const float4 cA = *(const float4*)&cw[0][col];
    const float4 cB = *(const float4*)&cw[1][col];
    const float4 cC = *(const float4*)&cw[2][col];

    const int gwarp  = (blockIdx.x * 256 + threadIdx.x) >> 5;
    const int nwarps = (gridDim.x * 256) >> 5;

    for (int e0 = gwarp; e0 < E; e0 += nwarps * 4) {
        int   se[4], de[4];
        float w0[4], w1[4], w2[4];
        float4 p[4];
        bool  v[4];

        #pragma unroll
        for (int u = 0; u < 4; u++) {
            int e = e0 + u * nwarps;
            v[u] = (e < E);
            if (v[u]) {
                se[u] = src[e];
                de[u] = dst[e];
                w0[u] = ew[e * 3 + 0];
                w1[u] = ew[e * 3 + 1];
                w2[u] = ew[e * 3 + 2];
            }
        }
        #pragma unroll
        for (int u = 0; u < 4; u++)
            if (v[u]) p[u] = *(const float4*)(g_P + (long)se[u] * 128 + col);

        #pragma unroll
        for (int u = 0; u < 4; u++) {
            if (!v[u]) continue;
            float t0 = p[u].x + w0[u] * cA.x + w1[u] * cB.x + w2[u] * cC.x;
            float t1 = p[u].y + w0[u] * cA.y + w1[u] * cB.y + w2[u] * cC.y;
            float t2 = p[u].z + w0[u] * cA.z + w1[u] * cB.z + w2[u] * cC.z;
            float t3 = p[u].w + w0[u] * cA.w + w1[u] * cB.w + w2[u] * cC.w;
            t0 = (t0 < 0.f) ? 0.01f * t0 : t0;
            t1 = (t1 < 0.f) ? 0.01f * t1 : t1;
            t2 = (t2 < 0.f) ? 0.01f * t2 : t2;
            t3 = (t3 < 0.f) ? 0.01f * t3 : t3;
            float* addr = g_sums + (long)de[u] * 128 + col;
            asm volatile("red.global.add.v4.f32 [%0], {%1, %2, %3, %4};"
                         :: "l"(addr), "f"(t0), "f"(t1), "f"(t2), "f"(t3)
                         : "memory");
            if (lane == 0) atomicAdd(&g_counts[de[u]], 1.0f);
        }
    }
}

// ---------------------------------------------------------------------------
extern "C" void kernel_launch(void* const* d_in, const int* in_sizes, int n_in,
                              void* d_out, int out_size)
{
    const float* h    = (const float*)d_in[0];
    const int*   esrc = (const int*)  d_in[1];
    const int*   edst = (const int*)  d_in[2];
    const float* ew   = (const float*)d_in[3];
    const float* W1   = (const float*)d_in[4];
    const float* b1   = (const float*)d_in[5];
    const float* W2   = (const float*)d_in[6];
    const float* b2   = (const float*)d_in[7];
    float* out = (float*)d_out;

    int M = in_sizes[0] / 128;    // 50000 nodes
    int E = in_sizes[1];          // 800000 edges
    int nT = (M + 127) / 128;     // 391 row tiles

    prep_kernel<<<512, 256>>>(W1, W2, M);
    gemm_mma_kernel<128, false, 1><<<nT, 256>>>(h, b1, nullptr, M);
    edge_kernel<<<1480, 256>>>(esrc, edst, ew, W1, E);
    gemm_mma_kernel<256, true, 2><<<nT, 256>>>(h, b2, out, M);
}